// round 12
// baseline (speedup 1.0000x reference)
#include <cuda_runtime.h>
#include <cstdint>

// CTRNN scan: PULL-model cluster exchange. Each CTA stores only its own
// 64-col state slice; peers read it in place via ld.shared::cluster during
// the mainloop. Per step the only cross-CTA traffic besides reads is ONE
// remote mbarrier arrive per peer. fp32 end-to-end.
// B=64, T=4096, F=128, H=512, O=10, DT=0.1.

#define T_STEPS   4096
#define F_IN      128
#define H_DIM     512
#define O_OUT     10
#define CLUSTER_N 8
#define NCOL      64
#define NTHREADS  512
#define GRID      128
#define DT_C      0.1f

typedef unsigned long long ull;

// own-slice state buffer: 32 rows x 32B; row j = local kpair (2j,2j+1):
//   [ {s2j(b0),s2j+1(b0),s2j(b1),s2j+1(b1)} | {same for b2,b3} ]
struct __align__(16) Smem {
    float s[3][256];             // 3 x 1KB (own slice only)
    double part[8][2][NCOL];     // [kq][bpair][h] = {b_even, b_odd}
    float xq[2][512];            // 64 rows x 32B, same packing (f as k)
    ull   mbar[3];               // count-8: 7 remote arrives + 1 local
};

__device__ __forceinline__ uint32_t smem_u32(const void* p) {
    uint32_t a;
    asm("{ .reg .u64 t; cvta.to.shared.u64 t, %1; cvt.u32.u64 %0, t; }"
        : "=r"(a) : "l"(p));
    return a;
}
__device__ __forceinline__ ull fma2(ull a, ull b, ull c) {
    ull d;
    asm("fma.rn.f32x2 %0, %1, %2, %3;" : "=l"(d) : "l"(a), "l"(b), "l"(c));
    return d;
}
__device__ __forceinline__ ull add2(ull a, ull b) {
    ull d;
    asm("add.rn.f32x2 %0, %1, %2;" : "=l"(d) : "l"(a), "l"(b));
    return d;
}
__device__ __forceinline__ ull packxy(float x, float y) {
    ull d;
    asm("mov.b64 %0, {%1, %2};" : "=l"(d) : "f"(x), "f"(y));
    return d;
}
__device__ __forceinline__ void unpack2(ull v, float& x, float& y) {
    asm("mov.b64 {%0, %1}, %2;" : "=f"(x), "=f"(y) : "l"(v));
}
__device__ __forceinline__ float tanh_fast(float x) {
    float y;
    asm("tanh.approx.f32 %0, %1;" : "=f"(y) : "f"(x));
    return y;
}
__device__ __forceinline__ void mbar_wait_cl(uint32_t m, uint32_t ph) {
    uint32_t done;
    asm volatile(
        "{\n\t.reg .pred p;\n\t"
        "mbarrier.try_wait.parity.acquire.cluster.shared::cta.b64 p, [%1], %2;\n\t"
        "selp.b32 %0, 1, 0, p;\n\t}"
        : "=r"(done) : "r"(m), "r"(ph) : "memory");
    while (!done) {
        asm volatile(
            "{\n\t.reg .pred p;\n\t"
            "mbarrier.try_wait.parity.acquire.cluster.shared::cta.b64 p, [%1], %2, 0x989680;\n\t"
            "selp.b32 %0, 1, 0, p;\n\t}"
            : "=r"(done) : "r"(m), "r"(ph) : "memory");
    }
}
__device__ __forceinline__ uint32_t mapa_u32(uint32_t la, uint32_t r) {
    uint32_t ra;
    asm("mapa.shared::cluster.u32 %0, %1, %2;" : "=r"(ra) : "r"(la), "r"(r));
    return ra;
}
// 16B remote (DSMEM) load as two u64 halves
__device__ __forceinline__ void ld_cl_16(uint32_t ra, ull& x, ull& y) {
    asm volatile("ld.shared::cluster.v2.b64 {%0, %1}, [%2];"
                 : "=l"(x), "=l"(y) : "r"(ra) : "memory");
}
__device__ __forceinline__ float ld_cl_f32(uint32_t ra) {
    uint32_t v;
    asm volatile("ld.shared::cluster.b32 %0, [%1];" : "=r"(v) : "r"(ra)
                 : "memory");
    return __uint_as_float(v);
}

__global__ void __cluster_dims__(CLUSTER_N, 1, 1) __launch_bounds__(NTHREADS, 1)
ctrnn_scan(const float* __restrict__ xg,   const float* __restrict__ ic,
           const float* __restrict__ Wing, const float* __restrict__ Wrecg,
           const float* __restrict__ bg,   const float* __restrict__ taug,
           const float* __restrict__ Rw,   const float* __restrict__ Rb,
           float* __restrict__ outg)
{
    __shared__ Smem sm;

    uint32_t rank;
    asm("mov.u32 %0, %%cluster_ctarank;" : "=r"(rank));
    const int tid = threadIdx.x;
    const int cl  = blockIdx.x / CLUSTER_N;
    const int c0  = (int)rank * NCOL;
    const int gb0 = cl * 4;

    const int h  = tid & 63;    // output column within slice
    const int kq = tid >> 6;    // k-subgroup: k = src*64 + kq*8 + (0..7)

    // ---- weights to registers: dual-k packed, per-src groups ----
    ull wr[32];                 // [src*4+m], k0 = src*64 + kq*8 + 2m
    #pragma unroll
    for (int i = 0; i < 32; i++) {
        const int src = i >> 2, m = i & 3;
        const int k0 = src * 64 + kq * 8 + 2 * m;
        wr[i] = packxy(Wrecg[k0 * H_DIM + c0 + h],
                       Wrecg[(k0 + 1) * H_DIM + c0 + h]);
    }
    ull wi[8];
    #pragma unroll
    for (int m = 0; m < 8; m++) {
        const int f0 = kq * 16 + 2 * m;
        wi[m] = packxy(Wing[f0 * H_DIM + c0 + h],
                       Wing[(f0 + 1) * H_DIM + c0 + h]);
    }

    // ---- epilogue params (tid<64): thread owns kpair ej, bpair ep ----
    const int ej = tid & 31, ep = tid >> 5;     // valid for tid<64
    float biasE = 0.f, biasO = 0.f, arE = 0.f, arO = 0.f;
    float s00 = 0.f, s01 = 0.f, s10 = 0.f, s11 = 0.f;
    if (tid < 64) {
        biasE = bg[c0 + 2 * ej];
        biasO = bg[c0 + 2 * ej + 1];
        arE   = DT_C / taug[c0 + 2 * ej];
        arO   = DT_C / taug[c0 + 2 * ej + 1];
        s00 = s01 = ic[c0 + 2 * ej];
        s10 = s11 = ic[c0 + 2 * ej + 1];
    }

    // ---- init: own slice of state buf0, x[0], mbarriers ----
    if (tid < 256)
        sm.s[0][tid] = ic[c0 + (tid >> 3) * 2 + (tid & 1)];
    const int xb = tid >> 7, xf = tid & 127;
    const uint32_t xoff = (uint32_t)((xf >> 1) * 32 + (xb >> 1) * 16
                                     + (xb & 1) * 8 + (xf & 1) * 4);
    sm.xq[0][xoff >> 2] = xg[(ull)(gb0 + xb) * T_STEPS * F_IN + xf];

    const uint32_t mbase = smem_u32(&sm.mbar[0]);
    const uint32_t sbase = smem_u32(&sm.s[0][0]);
    if (tid == 0) {
        #pragma unroll
        for (int i = 0; i < 3; i++)
            asm volatile("mbarrier.init.shared::cta.b64 [%0], %1;"
                         :: "r"(mbase + i * 8u), "r"(8) : "memory");
    }
    __syncthreads();
    asm volatile("barrier.cluster.arrive.aligned;" ::: "memory");
    asm volatile("barrier.cluster.wait.aligned;"   ::: "memory");

    const float* xsrc = xg + (ull)(gb0 + xb) * T_STEPS * F_IN + xf;
    const uint32_t kqoff = (uint32_t)(kq * 128);

    for (int t = 0; t < T_STEPS; t++) {
        const int cur  = t % 3;
        const int nbuf = (t + 1) % 3;
        const int cx   = t & 1;

        // prefetch x[t+1]
        float px = 0.f;
        if (t + 1 < T_STEPS) px = xsrc[(ull)(t + 1) * F_IN];

        // ---- x-projection FMAs: independent of s(t) ----
        ull a0 = 0, a1 = 0, a2 = 0, a3 = 0;
        {
            const char* xp = (const char*)&sm.xq[cx][0] + kq * 256;
            #pragma unroll
            for (int m = 0; m < 8; m++) {
                const double2 v0 = *(const double2*)(xp + m * 32);
                const double2 v1 = *(const double2*)(xp + m * 32 + 16);
                a0 = fma2(wi[m], __double_as_longlong(v0.x), a0);
                a1 = fma2(wi[m], __double_as_longlong(v0.y), a1);
                a2 = fma2(wi[m], __double_as_longlong(v1.x), a2);
                a3 = fma2(wi[m], __double_as_longlong(v1.y), a3);
            }
        }

        // ---- wait: all 8 sources have published s(t) in their own SMEM ----
        if (t > 0)
            mbar_wait_cl(mbase + (uint32_t)cur * 8u,
                         (((uint32_t)t - 1u) / 3u) & 1u);

        // ---- recurrent FMAs: read each source's slice IN PLACE (DSMEM) ----
        {
            const uint32_t sb = sbase + (uint32_t)cur * 1024u + kqoff;
            #pragma unroll
            for (int src = 0; src < CLUSTER_N; src++) {
                const uint32_t rb = mapa_u32(sb, (uint32_t)src);
                #pragma unroll
                for (int m = 0; m < 4; m++) {
                    ull vx, vy, ux, uy;
                    ld_cl_16(rb + m * 32u, vx, vy);
                    ld_cl_16(rb + m * 32u + 16u, ux, uy);
                    const ull wv = wr[src * 4 + m];
                    a0 = fma2(wv, vx, a0);
                    a1 = fma2(wv, vy, a1);
                    a2 = fma2(wv, ux, a2);
                    a3 = fma2(wv, uy, a3);
                }
            }
        }

        // horizontal add (even/odd k) and store partials
        {
            float e, o, f0, f1, f2, f3;
            unpack2(a0, e, o); f0 = e + o;
            unpack2(a1, e, o); f1 = e + o;
            unpack2(a2, e, o); f2 = e + o;
            unpack2(a3, e, o); f3 = e + o;
            sm.part[kq][0][h] = __longlong_as_double(packxy(f0, f1));
            sm.part[kq][1][h] = __longlong_as_double(packxy(f2, f3));
        }

        // stage x[t+1]
        if (t + 1 < T_STEPS) sm.xq[cx ^ 1][xoff >> 2] = px;

        __syncthreads();   // partials + staged x visible

        // ---- epilogue: 64 threads; LOCAL store + tiny remote arrives ----
        if (tid < 64) {
            const char* pb = (const char*)&sm.part[0][ep][2 * ej];
            ull vE = 0, vO = 0;
            #pragma unroll
            for (int q = 0; q < 8; q++) {
                const double2 d = *(const double2*)(pb + q * 1024);
                vE = add2(vE, __double_as_longlong(d.x));
                vO = add2(vO, __double_as_longlong(d.y));
            }
            float pEbE, pEbO, pObE, pObO;
            unpack2(vE, pEbE, pEbO);
            unpack2(vO, pObE, pObO);
            const float n00 = fmaf(arE, tanh_fast(pEbE + biasE) - s00, s00);
            const float n01 = fmaf(arE, tanh_fast(pEbO + biasE) - s01, s01);
            const float n10 = fmaf(arO, tanh_fast(pObE + biasO) - s10, s10);
            const float n11 = fmaf(arO, tanh_fast(pObO + biasO) - s11, s11);
            s00 = n00; s01 = n01; s10 = n10; s11 = n11;

            // own slice, local store only: row ej, half ep of buffer nbuf
            *(float4*)((char*)&sm.s[0][0] + (uint32_t)nbuf * 1024u
                       + (uint32_t)ej * 32u + (uint32_t)ep * 16u) =
                make_float4(n00, n10, n01, n11);

            asm volatile("bar.sync 1, 64;" ::: "memory");

            if (tid < 8) {
                // cumulative release of all 64 threads' stores
                asm volatile("fence.acq_rel.cluster;" ::: "memory");
                const uint32_t mb = mbase + (uint32_t)nbuf * 8u;
                if (tid < 7) {
                    const uint32_t peer = (uint32_t)tid
                                        + ((uint32_t)tid >= rank ? 1u : 0u);
                    const uint32_t ra = mapa_u32(mb, peer);
                    asm volatile(
                        "mbarrier.arrive.release.cluster.shared::cluster.b64 _, [%0];"
                        :: "r"(ra) : "memory");
                } else {
                    asm volatile(
                        "mbarrier.arrive.release.cta.shared::cta.b64 _, [%0];"
                        :: "r"(mb) : "memory");
                }
            }
        }
    }

    // ---- final wait + readout (rank 0 pulls peer slices) ----
    mbar_wait_cl(mbase + (uint32_t)(T_STEPS % 3) * 8u,
                 (((uint32_t)T_STEPS - 1u) / 3u) & 1u);
    __syncthreads();

    if (rank == 0) {
        const uint32_t fb = (uint32_t)(T_STEPS % 3) * 1024u;
        const int wid_ = tid >> 5, lane = tid & 31;
        for (int bo = wid_; bo < 4 * O_OUT; bo += NTHREADS / 32) {
            const int b = bo / O_OUT, o = bo % O_OUT;
            float acc = 0.f;
            for (int k = lane; k < H_DIM; k += 32) {
                const int src = k >> 6, kl = k & 63;
                const uint32_t idx = (uint32_t)((kl >> 1) * 8 + (b >> 1) * 4
                                               + (b & 1) * 2 + (kl & 1));
                const float sv = ld_cl_f32(
                    mapa_u32(sbase + fb + idx * 4u, (uint32_t)src));
                acc += sv * Rw[k * O_OUT + o];
            }
            #pragma unroll
            for (int off = 16; off; off >>= 1)
                acc += __shfl_xor_sync(0xffffffffu, acc, off);
            if (lane == 0) outg[(gb0 + b) * O_OUT + o] = acc + Rb[o];
        }
    }

    // exit safety: peers read this CTA's SMEM until their readout completes
    asm volatile("barrier.cluster.arrive.aligned;" ::: "memory");
    asm volatile("barrier.cluster.wait.aligned;"   ::: "memory");
}

extern "C" void kernel_launch(void* const* d_in, const int* in_sizes, int n_in,
                              void* d_out, int out_size)
{
    const float* x    = (const float*)d_in[0];
    const float* ic   = (const float*)d_in[1];
    const float* Win  = (const float*)d_in[2];
    const float* Wrec = (const float*)d_in[3];
    const float* b    = (const float*)d_in[4];
    const float* tau  = (const float*)d_in[5];
    const float* Rw   = (const float*)d_in[6];
    const float* Rb   = (const float*)d_in[7];
    float* out = (float*)d_out;
    (void)in_sizes; (void)n_in; (void)out_size;

    ctrnn_scan<<<GRID, NTHREADS>>>(x, ic, Win, Wrec, b, tau, Rw, Rb, out);
}

// round 14
// speedup vs baseline: 3.0345x; 3.0345x over previous
#include <cuda_runtime.h>
#include <cstdint>

// CTRNN scan: best-known (R7/13.27ms) kernel + 2-step-deep x prefetch
// pipeline so the x LDG can never expose DRAM latency into the per-step
// cluster sync chain. Interleaved kpair/batch state layout, dual-k f32x2
// register weights, ONE combined count-2 mbarrier per buffer (7KB tx from
// peer bulk copies + local release-arrive), triple-buffered state.
// B=64, T=4096, F=128, H=512, O=10, DT=0.1, fp32.

#define T_STEPS   4096
#define F_IN      128
#define H_DIM     512
#define O_OUT     10
#define CLUSTER_N 8
#define NCOL      64
#define NTHREADS  512
#define GRID      128
#define DT_C      0.1f
#define SLICE_BYTES  1024u                 // 32 rows x 32B (64 k x 4 b)
#define EXPECT_BYTES (7u * SLICE_BYTES)

typedef unsigned long long ull;

// state buffer: 256 rows x 32B; row j = kpair (2j,2j+1):
//   [ {s2j(b0),s2j+1(b0),s2j(b1),s2j+1(b1)} | {...b2,b3} ]
// rank r's slice = rows [32r,32r+32) = contiguous 1KB.
struct __align__(16) Smem {
    float s[3][2048];            // 3 x 8KB
    double part[8][2][NCOL];     // [kq][bpair][h] = {b_even, b_odd}
    float xq[2][512];            // 64 rows x 32B, same packing (f as k)
    ull   mbar[3];
};

__device__ __forceinline__ uint32_t smem_u32(const void* p) {
    uint32_t a;
    asm("{ .reg .u64 t; cvta.to.shared.u64 t, %1; cvt.u32.u64 %0, t; }"
        : "=r"(a) : "l"(p));
    return a;
}
__device__ __forceinline__ ull fma2(ull a, ull b, ull c) {
    ull d;
    asm("fma.rn.f32x2 %0, %1, %2, %3;" : "=l"(d) : "l"(a), "l"(b), "l"(c));
    return d;
}
__device__ __forceinline__ ull add2(ull a, ull b) {
    ull d;
    asm("add.rn.f32x2 %0, %1, %2;" : "=l"(d) : "l"(a), "l"(b));
    return d;
}
__device__ __forceinline__ ull packxy(float x, float y) {
    ull d;
    asm("mov.b64 %0, {%1, %2};" : "=l"(d) : "f"(x), "f"(y));
    return d;
}
__device__ __forceinline__ void unpack2(ull v, float& x, float& y) {
    asm("mov.b64 {%0, %1}, %2;" : "=f"(x), "=f"(y) : "l"(v));
}
__device__ __forceinline__ float tanh_fast(float x) {
    float y;
    asm("tanh.approx.f32 %0, %1;" : "=f"(y) : "f"(x));
    return y;
}
__device__ __forceinline__ void mbar_wait(uint32_t m, uint32_t ph) {
    uint32_t done;
    asm volatile(
        "{\n\t.reg .pred p;\n\t"
        "mbarrier.try_wait.parity.acquire.cta.shared::cta.b64 p, [%1], %2;\n\t"
        "selp.b32 %0, 1, 0, p;\n\t}"
        : "=r"(done) : "r"(m), "r"(ph) : "memory");
    while (!done) {
        asm volatile(
            "{\n\t.reg .pred p;\n\t"
            "mbarrier.try_wait.parity.acquire.cta.shared::cta.b64 p, [%1], %2, 0x989680;\n\t"
            "selp.b32 %0, 1, 0, p;\n\t}"
            : "=r"(done) : "r"(m), "r"(ph) : "memory");
    }
}
__device__ __forceinline__ void mbar_expect(uint32_t m) {
    asm volatile("mbarrier.arrive.expect_tx.shared::cta.b64 _, [%0], %1;"
                 :: "r"(m), "r"(EXPECT_BYTES) : "memory");
}
__device__ __forceinline__ void mbar_arrive(uint32_t m) {
    asm volatile("mbarrier.arrive.release.cta.shared::cta.b64 _, [%0];"
                 :: "r"(m) : "memory");
}
__device__ __forceinline__ uint32_t mapa_u32(uint32_t la, uint32_t r) {
    uint32_t ra;
    asm("mapa.shared::cluster.u32 %0, %1, %2;" : "=r"(ra) : "r"(la), "r"(r));
    return ra;
}
__device__ __forceinline__ void bulk_copy_peer(uint32_t dst, uint32_t src,
                                               uint32_t bytes, uint32_t rmbar) {
    asm volatile(
        "cp.async.bulk.shared::cluster.shared::cta.mbarrier::complete_tx::bytes "
        "[%0], [%1], %2, [%3];"
        :: "r"(dst), "r"(src), "r"(bytes), "r"(rmbar) : "memory");
}

__global__ void __cluster_dims__(CLUSTER_N, 1, 1) __launch_bounds__(NTHREADS, 1)
ctrnn_scan(const float* __restrict__ xg,   const float* __restrict__ ic,
           const float* __restrict__ Wing, const float* __restrict__ Wrecg,
           const float* __restrict__ bg,   const float* __restrict__ taug,
           const float* __restrict__ Rw,   const float* __restrict__ Rb,
           float* __restrict__ outg)
{
    __shared__ Smem sm;

    uint32_t rank;
    asm("mov.u32 %0, %%cluster_ctarank;" : "=r"(rank));
    const int tid = threadIdx.x;
    const int cl  = blockIdx.x / CLUSTER_N;
    const int c0  = (int)rank * NCOL;
    const int gb0 = cl * 4;

    const int h  = tid & 63;    // output column within slice
    const int kq = tid >> 6;    // k-subgroup: k = src*64 + kq*8 + (0..7)

    // ---- weights to registers: dual-k packed, per-src groups ----
    ull wr[32];
    #pragma unroll
    for (int i = 0; i < 32; i++) {
        const int src = i >> 2, m = i & 3;
        const int k0 = src * 64 + kq * 8 + 2 * m;
        wr[i] = packxy(Wrecg[k0 * H_DIM + c0 + h],
                       Wrecg[(k0 + 1) * H_DIM + c0 + h]);
    }
    ull wi[8];
    #pragma unroll
    for (int m = 0; m < 8; m++) {
        const int f0 = kq * 16 + 2 * m;
        wi[m] = packxy(Wing[f0 * H_DIM + c0 + h],
                       Wing[(f0 + 1) * H_DIM + c0 + h]);
    }

    // ---- epilogue params (tid<128) ----
    const int eh = tid & 63, ebp = (tid >> 6) & 1;
    float biasv = 0.f, arv = 0.f, sA = 0.f, sB = 0.f;
    if (tid < 128) {
        biasv = bg[c0 + eh];
        arv   = DT_C / taug[c0 + eh];
        sA = sB = ic[c0 + eh];
    }

    // ---- init: state buf0 (interleaved layout), x[0], mbarriers ----
    for (int i = tid; i < 2048; i += NTHREADS)
        sm.s[0][i] = ic[(i >> 3) * 2 + (i & 1)];
    const int xb = tid >> 7, xf = tid & 127;
    const uint32_t xoff = (uint32_t)((xf >> 1) * 32 + (xb >> 1) * 16
                                     + (xb & 1) * 8 + (xf & 1) * 4);
    sm.xq[0][xoff >> 2] = xg[(ull)(gb0 + xb) * T_STEPS * F_IN + xf];

    const uint32_t mbase = smem_u32(&sm.mbar[0]);
    const uint32_t sbase = smem_u32(&sm.s[0][0]);
    if (tid == 0) {
        #pragma unroll
        for (int i = 0; i < 3; i++)
            asm volatile("mbarrier.init.shared::cta.b64 [%0], %1;"
                         :: "r"(mbase + i * 8u), "r"(2) : "memory");
        #pragma unroll
        for (int i = 0; i < 3; i++) mbar_expect(mbase + i * 8u);
    }
    __syncthreads();
    asm volatile("barrier.cluster.arrive.aligned;" ::: "memory");
    asm volatile("barrier.cluster.wait.aligned;"   ::: "memory");

    const float* xsrc = xg + (ull)(gb0 + xb) * T_STEPS * F_IN + xf;

    // 2-deep x pipeline: px_stage holds x[t+1] (loaded at step t-1)
    float px_stage = xsrc[F_IN];   // x[1]

    for (int t = 0; t < T_STEPS; t++) {
        const int cur  = t % 3;
        const int nbuf = (t + 1) % 3;
        const int cx   = t & 1;

        // stage x[t+1] NOW (value was loaded a full step ago; the write
        // target xq[cx^1] had its last readers before sync(t-1))
        if (t + 1 < T_STEPS) sm.xq[cx ^ 1][xoff >> 2] = px_stage;

        // issue the LDG for x[t+2]: ~a full step of latency cover
        float px_next = 0.f;
        if (t + 2 < T_STEPS) px_next = xsrc[(ull)(t + 2) * F_IN];

        // ---- x-projection FMAs: independent of s(t) ----
        ull a0 = 0, a1 = 0, a2 = 0, a3 = 0;
        {
            const char* xp = (const char*)&sm.xq[cx][0] + kq * 256;
            #pragma unroll
            for (int m = 0; m < 8; m++) {
                const double2 v0 = *(const double2*)(xp + m * 32);
                const double2 v1 = *(const double2*)(xp + m * 32 + 16);
                a0 = fma2(wi[m], __double_as_longlong(v0.x), a0);
                a1 = fma2(wi[m], __double_as_longlong(v0.y), a1);
                a2 = fma2(wi[m], __double_as_longlong(v1.x), a2);
                a3 = fma2(wi[m], __double_as_longlong(v1.y), a3);
            }
        }

        // ---- single combined wait: 7 peer slices (tx) + own (arrive) ----
        if (t > 0) {
            const uint32_t m = mbase + (uint32_t)cur * 8u;
            mbar_wait(m, (((uint32_t)t - 1u) / 3u) & 1u);
            if (tid == 0) mbar_expect(m);    // re-arm for step t+3
        }

        // ---- recurrent FMAs: 8 srcs x 4 kpairs, mov-free ----
        {
            const char* sp = (const char*)&sm.s[cur][0] + kq * 128;
            #pragma unroll
            for (int i = 0; i < 32; i++) {
                const int src = i >> 2, m = i & 3;
                const char* rp = sp + src * 1024 + m * 32;
                const double2 v0 = *(const double2*)(rp);
                const double2 v1 = *(const double2*)(rp + 16);
                a0 = fma2(wr[i], __double_as_longlong(v0.x), a0);
                a1 = fma2(wr[i], __double_as_longlong(v0.y), a1);
                a2 = fma2(wr[i], __double_as_longlong(v1.x), a2);
                a3 = fma2(wr[i], __double_as_longlong(v1.y), a3);
            }
        }

        // horizontal add (even/odd k) and store partials
        {
            float e, o, f0, f1, f2, f3;
            unpack2(a0, e, o); f0 = e + o;
            unpack2(a1, e, o); f1 = e + o;
            unpack2(a2, e, o); f2 = e + o;
            unpack2(a3, e, o); f3 = e + o;
            sm.part[kq][0][h] = __longlong_as_double(packxy(f0, f1));
            sm.part[kq][1][h] = __longlong_as_double(packxy(f2, f3));
        }

        px_stage = px_next;   // rotate the x pipeline

        __syncthreads();   // partials + staged x visible

        // ---- epilogue: 4 warps ----
        if (tid < 128) {
            ull s8 = __double_as_longlong(sm.part[0][ebp][eh]);
            #pragma unroll
            for (int q = 1; q < 8; q++)
                s8 = add2(s8, __double_as_longlong(sm.part[q][ebp][eh]));
            float pA, pB;
            unpack2(s8, pA, pB);
            const float nA = fmaf(arv, tanh_fast(pA + biasv) - sA, sA);
            const float nB = fmaf(arv, tanh_fast(pB + biasv) - sB, sB);
            sA = nA; sB = nB;
            const int k = c0 + eh;
            float* dst = (float*)((char*)&sm.s[nbuf][0]
                        + (k >> 1) * 32 + ebp * 16 + (k & 1) * 4);
            dst[0] = nA;
            dst[2] = nB;

            asm volatile("bar.sync 1, 128;" ::: "memory");

            if (tid < 8) {
                const uint32_t src = sbase + (uint32_t)nbuf * 8192u
                                   + rank * SLICE_BYTES;
                const uint32_t rmb = mbase + (uint32_t)nbuf * 8u;
                if (tid < 7) {
                    asm volatile("fence.proxy.async.shared::cta;" ::: "memory");
                    const uint32_t peer = (uint32_t)tid
                                        + ((uint32_t)tid >= rank ? 1u : 0u);
                    bulk_copy_peer(mapa_u32(src, peer), src, SLICE_BYTES,
                                   mapa_u32(rmb, peer));
                } else {
                    mbar_arrive(rmb);   // own slice release
                }
            }
        }
    }

    // ---- final wait + readout ----
    mbar_wait(mbase + (uint32_t)(T_STEPS % 3) * 8u,
              (((uint32_t)T_STEPS - 1u) / 3u) & 1u);
    __syncthreads();

    if (rank == 0) {
        const float* sf = &sm.s[T_STEPS % 3][0];
        const int wid_ = tid >> 5, lane = tid & 31;
        for (int bo = wid_; bo < 4 * O_OUT; bo += NTHREADS / 32) {
            const int b = bo / O_OUT, o = bo % O_OUT;
            float acc = 0.f;
            for (int k = lane; k < H_DIM; k += 32)
                acc += sf[(k >> 1) * 8 + (b >> 1) * 4 + (b & 1) * 2 + (k & 1)]
                     * Rw[k * O_OUT + o];
            #pragma unroll
            for (int off = 16; off; off >>= 1)
                acc += __shfl_xor_sync(0xffffffffu, acc, off);
            if (lane == 0) outg[(gb0 + b) * O_OUT + o] = acc + Rb[o];
        }
    }

    // exit safety: peer copies may still target this CTA's SMEM
    asm volatile("barrier.cluster.arrive.aligned;" ::: "memory");
    asm volatile("barrier.cluster.wait.aligned;"   ::: "memory");
}

extern "C" void kernel_launch(void* const* d_in, const int* in_sizes, int n_in,
                              void* d_out, int out_size)
{
    const float* x    = (const float*)d_in[0];
    const float* ic   = (const float*)d_in[1];
    const float* Win  = (const float*)d_in[2];
    const float* Wrec = (const float*)d_in[3];
    const float* b    = (const float*)d_in[4];
    const float* tau  = (const float*)d_in[5];
    const float* Rw   = (const float*)d_in[6];
    const float* Rb   = (const float*)d_in[7];
    float* out = (float*)d_out;
    (void)in_sizes; (void)n_in; (void)out_size;

    ctrnn_scan<<<GRID, NTHREADS>>>(x, ic, Win, Wrec, b, tau, Rw, Rb, out);
}